// round 10
// baseline (speedup 1.0000x reference)
#include <cuda_runtime.h>
#include <cuda_fp16.h>
#include <math.h>
#include <stdint.h>

// ---------------- problem constants ----------------
static constexpr int NUSERS = 100000;
static constexpr int NITEMS = 50000;
static constexpr int NNODE  = 150000;       // NUSERS + NITEMS
static constexpr int NEDGE  = 1200000;      // 2 * 600000
static constexpr int DIM    = 64;
static constexpr int PB     = 147;          // prep blocks (one wave, <=148 SMs)
static constexpr int PT     = 1024;
static constexpr int PTH    = PB * PT;      // 150528 threads
static constexpr int GCAP   = 1024;         // staged edges per gather block

// ---------------- device scratch (static; no runtime alloc) ----------------
// Invariants at kernel_launch entry (static init covers call 1; the final
// kernel re-establishes them at the end of every call):
//   g_wdeg == 0, g_cnt == 0, g_barc == 0
__device__ float    g_edge_w[NEDGE];
__device__ int2     g_edge[NEDGE];          // {src, __float_as_int(edge_w * dinv[src])}
__device__ float    g_wdeg[NNODE];
__device__ float    g_dinv[NNODE];
__device__ int      g_cnt[NNODE];
__device__ int      g_rowptr[NNODE + 1];
__device__ int      g_cursor[NNODE];
__device__ int      g_bsum[PB];
__device__ unsigned g_barc[3];
__device__ __half   g_x0[(size_t)NNODE * DIM];
__device__ __half   g_x1[(size_t)NNODE * DIM];
__device__ __half   g_x2[(size_t)NNODE * DIM];
__device__ __half* const g_xptr[3] = {g_x0, g_x1, g_x2};

// grid barrier for the one-wave prep kernel (all PB blocks resident).
__device__ __forceinline__ void gbar(int i) {
    __syncthreads();
    if (threadIdx.x == 0) {
        __threadfence();
        atomicAdd(&g_barc[i], 1u);
        while (*(volatile unsigned*)&g_barc[i] < (unsigned)PB) __nanosleep(64);
        __threadfence();
    }
    __syncthreads();
}

// ---------------- fused preprocessing: mlp -> scan -> scatter + init ----------------
__global__ void __launch_bounds__(1024) prep_kernel(
        const float* __restrict__ ef,
        const float* __restrict__ w1,    const float* __restrict__ b1,
        const float* __restrict__ w2,    const float* __restrict__ b2,
        const int*   __restrict__ eidx,
        const float* __restrict__ uemb,  const float* __restrict__ audio,
        const float* __restrict__ art,   const float* __restrict__ alb,
        const int*   __restrict__ aid,   const int*   __restrict__ bid) {
    __shared__ float sW1[256], sB1[32], sW2[32], sB2s[1];
    __shared__ int   sums[256];
    __shared__ int   ssc[1024];
    int t  = threadIdx.x;
    int gt = blockIdx.x * 1024 + t;

    if (t < 256) sW1[t] = w1[t];
    if (t < 32)  { sB1[t] = b1[t]; sW2[t] = w2[t]; }
    if (t == 0)  sB2s[0] = b2[0];
    __syncthreads();
    float sB2 = sB2s[0];

    // -------- phase A: edge MLP + wdeg/cnt histogram --------
    for (int e = gt; e < NEDGE; e += PTH) {
        const float4* fp = reinterpret_cast<const float4*>(ef + (size_t)e * 8);
        float4 fa = __ldg(fp);
        float4 fb = __ldg(fp + 1);
        float f[8] = {fa.x, fa.y, fa.z, fa.w, fb.x, fb.y, fb.z, fb.w};
        float o = sB2;
        #pragma unroll
        for (int j = 0; j < 32; j++) {
            float h = sB1[j];
            #pragma unroll
            for (int i = 0; i < 8; i++) h = fmaf(f[i], sW1[i * 32 + j], h);
            h = fmaxf(h, 0.f);
            o = fmaf(h, sW2[j], o);
        }
        float wv = 1.f / (1.f + expf(-o));
        g_edge_w[e] = wv;
        int c = __ldg(&eidx[NEDGE + e]);
        atomicAdd(&g_wdeg[c], wv);
        atomicAdd(&g_cnt[c], 1);
    }
    gbar(0);

    // -------- phase B: per-block sums of g_cnt --------
    int n  = gt;
    int cn = (n < NNODE) ? g_cnt[n] : 0;
    ssc[t] = cn;
    __syncthreads();
    for (int off = 512; off > 0; off >>= 1) {
        if (t < off) ssc[t] += ssc[t + off];
        __syncthreads();
    }
    if (t == 0) g_bsum[blockIdx.x] = ssc[0];
    gbar(1);

    // -------- phase C: redundant scan of block sums + local scan --------
    if (t < 256) sums[t] = (t < PB) ? g_bsum[t] : 0;
    __syncthreads();
    for (int off = 1; off < 256; off <<= 1) {
        int v = (t < 256 && t >= off) ? sums[t - off] : 0;
        __syncthreads();
        if (t < 256) sums[t] += v;
        __syncthreads();
    }
    int blockOff = (blockIdx.x == 0) ? 0 : sums[blockIdx.x - 1];

    ssc[t] = cn;
    __syncthreads();
    for (int off = 1; off < 1024; off <<= 1) {
        int v = (t >= off) ? ssc[t - off] : 0;
        __syncthreads();
        ssc[t] += v;
        __syncthreads();
    }
    if (n < NNODE) {
        int p = blockOff + ssc[t] - cn;
        g_rowptr[n] = p;
        g_cursor[n] = p;
        float dg = g_wdeg[n];
        g_dinv[n] = (dg > 0.f) ? rsqrtf(dg) : 0.f;
    }
    if (blockIdx.x == 0 && t == 0) g_rowptr[NNODE] = NEDGE;
    gbar(2);

    // -------- phase D: scatter (2 edges/thread) + node init --------
    for (int p = gt; p < NEDGE / 2; p += PTH) {
        int e = p * 2;
        int2   r2 = __ldg(reinterpret_cast<const int2*>(eidx + e));
        int2   c2 = __ldg(reinterpret_cast<const int2*>(eidx + NEDGE + e));
        float2 w2v = __ldg(reinterpret_cast<const float2*>(g_edge_w + e));

        float wa = w2v.x * __ldg(&g_dinv[r2.x]);
        int pa = atomicAdd(&g_cursor[c2.x], 1);
        g_edge[pa] = make_int2(r2.x, __float_as_int(wa));

        float wb = w2v.y * __ldg(&g_dinv[r2.y]);
        int pb = atomicAdd(&g_cursor[c2.y], 1);
        g_edge[pb] = make_int2(r2.y, __float_as_int(wb));
    }

    // init: x0 = [ l2norm(user) ; l2norm(0.3*audio + 0.44*(artist+album)) ]
    for (int v = gt; v < NNODE * 16; v += PTH) {   // cutoffs are warp-aligned
        int node = v >> 4;
        int sub  = v & 15;
        float4 x;
        if (node < NUSERS) {
            x = __ldg(reinterpret_cast<const float4*>(uemb) + (size_t)node * 16 + sub);
        } else {
            int i = node - NUSERS;
            int a = __ldg(&aid[i]);
            int b = __ldg(&bid[i]);
            float4 pa = __ldg(reinterpret_cast<const float4*>(audio) + (size_t)i * 16 + sub);
            float4 pr = __ldg(reinterpret_cast<const float4*>(art)   + (size_t)a * 16 + sub);
            float4 pl = __ldg(reinterpret_cast<const float4*>(alb)   + (size_t)b * 16 + sub);
            x.x = pa.x * 0.3f + (pr.x + pl.x) * 0.44f;
            x.y = pa.y * 0.3f + (pr.y + pl.y) * 0.44f;
            x.z = pa.z * 0.3f + (pr.z + pl.z) * 0.44f;
            x.w = pa.w * 0.3f + (pr.w + pl.w) * 0.44f;
        }
        float ss = x.x * x.x + x.y * x.y + x.z * x.z + x.w * x.w;
        #pragma unroll
        for (int o = 8; o > 0; o >>= 1) ss += __shfl_xor_sync(0xffffffffu, ss, o);
        float inv = 1.f / fmaxf(sqrtf(ss), 1e-12f);

        __half2 h0 = __floats2half2_rn(x.x * inv, x.y * inv);
        __half2 h1 = __floats2half2_rn(x.z * inv, x.w * inv);
        uint2 hv;
        hv.x = *reinterpret_cast<unsigned int*>(&h0);
        hv.y = *reinterpret_cast<unsigned int*>(&h1);
        reinterpret_cast<uint2*>(g_x0)[(size_t)node * 16 + sub] = hv;
    }
}

// ---------------- block-staged gather ----------------
// Block = 8 warps = 8 consecutive nodes (18750 * 8 == 150000 exactly).
// Edge meta staged in smem zero-padded to multiples of 8 per node; inner loop
// is branch-free groups of 8 independent 128B row loads (4B/lane).
// Returns each lane's accumulated dims {2*lane, 2*lane+1} (pre-dinv).
struct GShared {
    int   rp[9];
    float dv[8];
    int   off[9];      // off[8] = padded total
    int2  meta[GCAP];
};

__device__ __forceinline__ float2 gather_staged(GShared& sm,
        const unsigned* __restrict__ xin, int base, int w, int lane, int t) {
    if (t < 9) sm.rp[t] = __ldg(&g_rowptr[base + t]);
    if (t < 8) sm.dv[t] = __ldg(&g_dinv[base + t]);
    __syncthreads();
    if (w == 0) {
        int deg = (lane < 8) ? sm.rp[lane + 1] - sm.rp[lane] : 0;
        int pd  = (deg + 7) & ~7;
        int s = pd;
        #pragma unroll
        for (int k = 1; k < 8; k <<= 1) {
            int v = __shfl_up_sync(0xffffffffu, s, k);
            if (lane >= k) s += v;
        }
        if (lane < 8) sm.off[lane] = s - pd;
        if (lane == 7) sm.off[8] = s;
    }
    __syncthreads();
    int total = sm.off[8];

    float a0 = 0.f, a1 = 0.f;
    if (total <= GCAP) {
        {   // stage: warp w pads+copies its node's segment
            int beg = sm.rp[w];
            int deg = sm.rp[w + 1] - beg;
            int off = sm.off[w];
            int pd  = (deg + 7) & ~7;
            for (int i = lane; i < pd; i += 32)
                sm.meta[off + i] = (i < deg) ? __ldg(&g_edge[beg + i]) : make_int2(0, 0);
        }
        __syncthreads();
        int off = sm.off[w];
        int pd  = sm.off[w + 1] - off;
        for (int i = 0; i < pd; i += 8) {
            int2 m[8]; unsigned v[8];
            #pragma unroll
            for (int k = 0; k < 8; k++) m[k] = sm.meta[off + i + k];
            #pragma unroll
            for (int k = 0; k < 8; k++) v[k] = __ldg(xin + (size_t)m[k].x * 32 + lane);
            #pragma unroll
            for (int k = 0; k < 8; k++) {
                float2 f = __half22float2(*reinterpret_cast<__half2*>(&v[k]));
                float wk = __int_as_float(m[k].y);
                a0 = fmaf(wk, f.x, a0);
                a1 = fmaf(wk, f.y, a1);
            }
        }
    } else {
        __syncthreads();   // match the staged path's barrier
        int beg = sm.rp[w];
        int end = sm.rp[w + 1];
        for (int e = beg; e < end; e++) {
            int2 m = __ldg(&g_edge[e]);
            unsigned v = __ldg(xin + (size_t)m.x * 32 + lane);
            float2 f = __half22float2(*reinterpret_cast<__half2*>(&v));
            float wk = __int_as_float(m.y);
            a0 = fmaf(wk, f.x, a0);
            a1 = fmaf(wk, f.y, a1);
        }
    }
    return make_float2(a0, a1);
}

// layers 0,1: x[l+1][n] = dinv[n] * sum   (fp16 out, fully coalesced)
__global__ void __launch_bounds__(256) gather_kernel(int layer) {
    __shared__ GShared sm;
    const unsigned* xin  = reinterpret_cast<const unsigned*>(g_xptr[layer]);
    unsigned*       xout = reinterpret_cast<unsigned*>(g_xptr[layer + 1]);

    int t = threadIdx.x, w = t >> 5, lane = t & 31;
    int base = blockIdx.x * 8;

    float2 a = gather_staged(sm, xin, base, w, lane, t);
    float dv = sm.dv[w];
    __half2 h = __floats2half2_rn(a.x * dv, a.y * dv);
    xout[(size_t)(base + w) * 32 + lane] = *reinterpret_cast<unsigned*>(&h);
}

// layer 2 fused with final: out = l2norm((x0+x1+x2+x3)/4), x3 kept fp32.
// Re-establishes the zero-invariants (wdeg, cnt, barrier counters).
__global__ void __launch_bounds__(256) gatherfinal_kernel(float* __restrict__ out) {
    __shared__ GShared sm;
    int t = threadIdx.x, w = t >> 5, lane = t & 31;
    int gt = blockIdx.x * 256 + t;
    if (gt < NNODE) { g_wdeg[gt] = 0.f; g_cnt[gt] = 0; }
    if (gt < 3)  g_barc[gt] = 0;
    if (gt == 0) out[(size_t)NNODE * DIM] = 0.f;   // align_loss scalar

    int base = blockIdx.x * 8;
    float2 a = gather_staged(sm, reinterpret_cast<const unsigned*>(g_x2), base, w, lane, t);
    int node = base + w;
    float dv = sm.dv[w];
    float s0 = a.x * dv;
    float s1 = a.y * dv;

    #pragma unroll
    for (int l = 0; l < 3; l++) {
        unsigned v = __ldg(reinterpret_cast<const unsigned*>(g_xptr[l]) + (size_t)node * 32 + lane);
        float2 f = __half22float2(*reinterpret_cast<__half2*>(&v));
        s0 += f.x;
        s1 += f.y;
    }
    s0 *= 0.25f;
    s1 *= 0.25f;
    float ss = fmaf(s0, s0, s1 * s1);
    #pragma unroll
    for (int o = 16; o > 0; o >>= 1) ss += __shfl_xor_sync(0xffffffffu, ss, o);
    float inv = 1.f / fmaxf(sqrtf(ss), 1e-12f);

    reinterpret_cast<float2*>(out)[(size_t)node * 32 + lane] = make_float2(s0 * inv, s1 * inv);
}

// ---------------- launcher ----------------
extern "C" void kernel_launch(void* const* d_in, const int* in_sizes, int n_in,
                              void* d_out, int out_size) {
    const float* uemb  = (const float*)d_in[0];
    const float* audio = (const float*)d_in[1];
    const float* art   = (const float*)d_in[2];
    const float* alb   = (const float*)d_in[3];
    const float* w1    = (const float*)d_in[4];
    const float* b1    = (const float*)d_in[5];
    const float* w2    = (const float*)d_in[6];
    const float* b2    = (const float*)d_in[7];
    const float* ef    = (const float*)d_in[8];
    const int*   eidx  = (const int*)  d_in[9];
    const int*   aid   = (const int*)  d_in[10];
    const int*   bid   = (const int*)  d_in[11];
    float* out = (float*)d_out;

    const int gatherBlocks = NNODE / 8;   // 18750, exact

    prep_kernel       <<<PB, PT>>>(ef, w1, b1, w2, b2, eidx,
                                   uemb, audio, art, alb, aid, bid);
    gather_kernel     <<<gatherBlocks, 256>>>(0);   // x0 -> x1
    gather_kernel     <<<gatherBlocks, 256>>>(1);   // x1 -> x2
    gatherfinal_kernel<<<gatherBlocks, 256>>>(out); // x2 -> out (fused final)
}

// round 11
// speedup vs baseline: 1.0961x; 1.0961x over previous
#include <cuda_runtime.h>
#include <cuda_fp16.h>
#include <math.h>
#include <stdint.h>

// ---------------- problem constants ----------------
static constexpr int NUSERS = 100000;
static constexpr int NITEMS = 50000;
static constexpr int NNODE  = 150000;       // NUSERS + NITEMS
static constexpr int NEDGE  = 1200000;      // 2 * 600000
static constexpr int DIM    = 64;
static constexpr int PB     = 147;          // prep blocks (one wave, <=148 SMs)
static constexpr int PT     = 1024;
static constexpr int PTH    = PB * PT;      // 150528 threads

// ---------------- device scratch (static; no runtime alloc) ----------------
// Invariants at kernel_launch entry (static init covers call 1; the final
// kernel re-establishes them at the end of every call):
//   g_wdeg == 0, g_cnt == 0, g_barc == 0
__device__ float    g_edge_w[NEDGE];
__device__ int2     g_edge[NEDGE];          // {src, __float_as_int(edge_w * dinv[src])}
__device__ float    g_wdeg[NNODE];
__device__ float    g_dinv[NNODE];
__device__ int      g_cnt[NNODE];
__device__ int      g_rowptr[NNODE + 1];
__device__ int      g_cursor[NNODE];
__device__ int      g_bsum[PB];
__device__ unsigned g_barc[3];
__device__ __half   g_x0[(size_t)NNODE * DIM];
__device__ __half   g_x1[(size_t)NNODE * DIM];
__device__ __half   g_x2[(size_t)NNODE * DIM];
__device__ __half* const g_xptr[3] = {g_x0, g_x1, g_x2};

// grid barrier for the one-wave prep kernel (all PB blocks resident).
__device__ __forceinline__ void gbar(int i) {
    __syncthreads();
    if (threadIdx.x == 0) {
        __threadfence();
        atomicAdd(&g_barc[i], 1u);
        while (*(volatile unsigned*)&g_barc[i] < (unsigned)PB) __nanosleep(64);
        __threadfence();
    }
    __syncthreads();
}

// ---------------- fused preprocessing: mlp -> scan -> scatter + init ----------------
__global__ void __launch_bounds__(1024) prep_kernel(
        const float* __restrict__ ef,
        const float* __restrict__ w1,    const float* __restrict__ b1,
        const float* __restrict__ w2,    const float* __restrict__ b2,
        const int*   __restrict__ eidx,
        const float* __restrict__ uemb,  const float* __restrict__ audio,
        const float* __restrict__ art,   const float* __restrict__ alb,
        const int*   __restrict__ aid,   const int*   __restrict__ bid) {
    __shared__ float sW1[256], sB1[32], sW2[32], sB2s[1];
    __shared__ int   sums[256];
    __shared__ int   ssc[1024];
    int t  = threadIdx.x;
    int gt = blockIdx.x * 1024 + t;

    if (t < 256) sW1[t] = w1[t];
    if (t < 32)  { sB1[t] = b1[t]; sW2[t] = w2[t]; }
    if (t == 0)  sB2s[0] = b2[0];
    __syncthreads();
    float sB2 = sB2s[0];

    // -------- phase A: edge MLP + wdeg/cnt histogram --------
    for (int e = gt; e < NEDGE; e += PTH) {
        const float4* fp = reinterpret_cast<const float4*>(ef + (size_t)e * 8);
        float4 fa = __ldg(fp);
        float4 fb = __ldg(fp + 1);
        float f[8] = {fa.x, fa.y, fa.z, fa.w, fb.x, fb.y, fb.z, fb.w};
        float o = sB2;
        #pragma unroll
        for (int j = 0; j < 32; j++) {
            float h = sB1[j];
            #pragma unroll
            for (int i = 0; i < 8; i++) h = fmaf(f[i], sW1[i * 32 + j], h);
            h = fmaxf(h, 0.f);
            o = fmaf(h, sW2[j], o);
        }
        float wv = 1.f / (1.f + expf(-o));
        g_edge_w[e] = wv;
        int c = __ldg(&eidx[NEDGE + e]);
        atomicAdd(&g_wdeg[c], wv);
        atomicAdd(&g_cnt[c], 1);
    }
    gbar(0);

    // -------- phase B: per-block sums of g_cnt --------
    int n  = gt;
    int cn = (n < NNODE) ? g_cnt[n] : 0;
    ssc[t] = cn;
    __syncthreads();
    for (int off = 512; off > 0; off >>= 1) {
        if (t < off) ssc[t] += ssc[t + off];
        __syncthreads();
    }
    if (t == 0) g_bsum[blockIdx.x] = ssc[0];
    gbar(1);

    // -------- phase C: redundant scan of block sums + local scan --------
    if (t < 256) sums[t] = (t < PB) ? g_bsum[t] : 0;
    __syncthreads();
    for (int off = 1; off < 256; off <<= 1) {
        int v = (t < 256 && t >= off) ? sums[t - off] : 0;
        __syncthreads();
        if (t < 256) sums[t] += v;
        __syncthreads();
    }
    int blockOff = (blockIdx.x == 0) ? 0 : sums[blockIdx.x - 1];

    ssc[t] = cn;
    __syncthreads();
    for (int off = 1; off < 1024; off <<= 1) {
        int v = (t >= off) ? ssc[t - off] : 0;
        __syncthreads();
        ssc[t] += v;
        __syncthreads();
    }
    if (n < NNODE) {
        int p = blockOff + ssc[t] - cn;
        g_rowptr[n] = p;
        g_cursor[n] = p;
        float dg = g_wdeg[n];
        g_dinv[n] = (dg > 0.f) ? rsqrtf(dg) : 0.f;
    }
    if (blockIdx.x == 0 && t == 0) g_rowptr[NNODE] = NEDGE;
    gbar(2);

    // -------- phase D: scatter (2 edges/thread) + node init --------
    for (int p = gt; p < NEDGE / 2; p += PTH) {
        int e = p * 2;
        int2   r2 = __ldg(reinterpret_cast<const int2*>(eidx + e));
        int2   c2 = __ldg(reinterpret_cast<const int2*>(eidx + NEDGE + e));
        float2 w2v = __ldg(reinterpret_cast<const float2*>(g_edge_w + e));

        float wa = w2v.x * __ldg(&g_dinv[r2.x]);
        int pa = atomicAdd(&g_cursor[c2.x], 1);
        g_edge[pa] = make_int2(r2.x, __float_as_int(wa));

        float wb = w2v.y * __ldg(&g_dinv[r2.y]);
        int pb = atomicAdd(&g_cursor[c2.y], 1);
        g_edge[pb] = make_int2(r2.y, __float_as_int(wb));
    }

    // init: x0 = [ l2norm(user) ; l2norm(0.3*audio + 0.44*(artist+album)) ]
    for (int v = gt; v < NNODE * 16; v += PTH) {   // cutoffs are warp-aligned
        int node = v >> 4;
        int sub  = v & 15;
        float4 x;
        if (node < NUSERS) {
            x = __ldg(reinterpret_cast<const float4*>(uemb) + (size_t)node * 16 + sub);
        } else {
            int i = node - NUSERS;
            int a = __ldg(&aid[i]);
            int b = __ldg(&bid[i]);
            float4 pa = __ldg(reinterpret_cast<const float4*>(audio) + (size_t)i * 16 + sub);
            float4 pr = __ldg(reinterpret_cast<const float4*>(art)   + (size_t)a * 16 + sub);
            float4 pl = __ldg(reinterpret_cast<const float4*>(alb)   + (size_t)b * 16 + sub);
            x.x = pa.x * 0.3f + (pr.x + pl.x) * 0.44f;
            x.y = pa.y * 0.3f + (pr.y + pl.y) * 0.44f;
            x.z = pa.z * 0.3f + (pr.z + pl.z) * 0.44f;
            x.w = pa.w * 0.3f + (pr.w + pl.w) * 0.44f;
        }
        float ss = x.x * x.x + x.y * x.y + x.z * x.z + x.w * x.w;
        #pragma unroll
        for (int o = 8; o > 0; o >>= 1) ss += __shfl_xor_sync(0xffffffffu, ss, o);
        float inv = 1.f / fmaxf(sqrtf(ss), 1e-12f);

        __half2 h0 = __floats2half2_rn(x.x * inv, x.y * inv);
        __half2 h1 = __floats2half2_rn(x.z * inv, x.w * inv);
        uint2 hv;
        hv.x = *reinterpret_cast<unsigned int*>(&h0);
        hv.y = *reinterpret_cast<unsigned int*>(&h1);
        reinterpret_cast<uint2*>(g_x0)[(size_t)node * 16 + sub] = hv;
    }
}

// ---- gather body (round-9 winner): warp = 1 node, lane owns dims {2l,2l+1} ----
// Edge meta for up to 32 edges staged in ONE coalesced int2 load; each edge is
// ONE warp-wide 128B row load (4B/lane). 8 independent loads in flight per
// group; padded edges contribute w=0 (src=0 is a valid, safe row).
__device__ __forceinline__ float2 gather_body(const unsigned* __restrict__ xin,
                                              int node, int lane) {
    int rp  = __ldg(&g_rowptr[node + (lane & 1)]);
    int beg = __shfl_sync(0xffffffffu, rp, 0);
    int end = __shfl_sync(0xffffffffu, rp, 1);
    int deg = end - beg;

    float a0 = 0.f, a1 = 0.f;
    for (int base = 0; base < deg; base += 32) {
        int idx = base + lane;
        int2 m = (idx < deg) ? __ldg(&g_edge[beg + idx]) : make_int2(0, 0);
        int nr = (min(deg - base, 32) + 7) & ~7;   // round up to group of 8
        for (int g = 0; g < nr; g += 8) {
            unsigned v[8];
            float    w[8];
            #pragma unroll
            for (int k = 0; k < 8; k++) {
                int src = __shfl_sync(0xffffffffu, m.x, g + k);
                w[k] = __int_as_float(__shfl_sync(0xffffffffu, m.y, g + k));
                v[k] = __ldg(xin + (size_t)src * 32 + lane);
            }
            #pragma unroll
            for (int k = 0; k < 8; k++) {
                float2 f = __half22float2(*reinterpret_cast<__half2*>(&v[k]));
                a0 = fmaf(w[k], f.x, a0);
                a1 = fmaf(w[k], f.y, a1);
            }
        }
    }
    return make_float2(a0, a1);
}

// layers 0,1: x[l+1][n] = dinv[n] * sum  (fp16 out, fully coalesced store)
__global__ void __launch_bounds__(256) gather_kernel(int layer) {
    const unsigned* __restrict__ xin  = reinterpret_cast<const unsigned*>(g_xptr[layer]);
    unsigned*       __restrict__ xout = reinterpret_cast<unsigned*>(g_xptr[layer + 1]);

    int warp = (blockIdx.x * blockDim.x + threadIdx.x) >> 5;
    int lane = threadIdx.x & 31;
    if (warp >= NNODE) return;

    float2 a = gather_body(xin, warp, lane);
    float dv = __ldg(&g_dinv[warp]);
    __half2 h = __floats2half2_rn(a.x * dv, a.y * dv);
    xout[(size_t)warp * 32 + lane] = *reinterpret_cast<unsigned*>(&h);
}

// layer 2 fused with final: out = l2norm((x0+x1+x2+x3)/4), x3 kept fp32.
// Re-establishes zero-invariants (wdeg, cnt, barrier counters).
__global__ void __launch_bounds__(256) gatherfinal_kernel(float* __restrict__ out) {
    int gt = blockIdx.x * blockDim.x + threadIdx.x;
    if (gt < NNODE) { g_wdeg[gt] = 0.f; g_cnt[gt] = 0; }
    if (gt < 3)  g_barc[gt] = 0;
    if (gt == 0) out[(size_t)NNODE * DIM] = 0.f;   // align_loss scalar

    int warp = gt >> 5;
    int lane = threadIdx.x & 31;
    if (warp >= NNODE) return;

    float2 a = gather_body(reinterpret_cast<const unsigned*>(g_x2), warp, lane);
    float dv = __ldg(&g_dinv[warp]);
    float s0 = a.x * dv;
    float s1 = a.y * dv;

    #pragma unroll
    for (int l = 0; l < 3; l++) {
        unsigned v = __ldg(reinterpret_cast<const unsigned*>(g_xptr[l]) + (size_t)warp * 32 + lane);
        float2 f = __half22float2(*reinterpret_cast<__half2*>(&v));
        s0 += f.x;
        s1 += f.y;
    }
    s0 *= 0.25f;
    s1 *= 0.25f;
    float ss = fmaf(s0, s0, s1 * s1);
    #pragma unroll
    for (int o = 16; o > 0; o >>= 1) ss += __shfl_xor_sync(0xffffffffu, ss, o);
    float inv = 1.f / fmaxf(sqrtf(ss), 1e-12f);

    reinterpret_cast<float2*>(out)[(size_t)warp * 32 + lane] = make_float2(s0 * inv, s1 * inv);
}

// ---------------- launcher ----------------
extern "C" void kernel_launch(void* const* d_in, const int* in_sizes, int n_in,
                              void* d_out, int out_size) {
    const float* uemb  = (const float*)d_in[0];
    const float* audio = (const float*)d_in[1];
    const float* art   = (const float*)d_in[2];
    const float* alb   = (const float*)d_in[3];
    const float* w1    = (const float*)d_in[4];
    const float* b1    = (const float*)d_in[5];
    const float* w2    = (const float*)d_in[6];
    const float* b2    = (const float*)d_in[7];
    const float* ef    = (const float*)d_in[8];
    const int*   eidx  = (const int*)  d_in[9];
    const int*   aid   = (const int*)  d_in[10];
    const int*   bid   = (const int*)  d_in[11];
    float* out = (float*)d_out;

    const int warpBlocks = (NNODE * 32 + 255) / 256;   // one warp per node

    prep_kernel       <<<PB, PT>>>(ef, w1, b1, w2, b2, eidx,
                                   uemb, audio, art, alb, aid, bid);
    gather_kernel     <<<warpBlocks, 256>>>(0);   // x0 -> x1
    gather_kernel     <<<warpBlocks, 256>>>(1);   // x1 -> x2
    gatherfinal_kernel<<<warpBlocks, 256>>>(out); // x2 -> out (fused final)
}

// round 12
// speedup vs baseline: 1.1214x; 1.0231x over previous
#include <cuda_runtime.h>
#include <cuda_fp16.h>
#include <math.h>
#include <stdint.h>

// ---------------- problem constants ----------------
static constexpr int NUSERS = 100000;
static constexpr int NITEMS = 50000;
static constexpr int NNODE  = 150000;       // NUSERS + NITEMS
static constexpr int NEDGE  = 1200000;      // 2 * 600000
static constexpr int DIM    = 64;
static constexpr int SCANB  = (NNODE + 1023) / 1024;     // 147 scan blocks
static constexpr int EDGE2B = (NEDGE / 2 + 255) / 256;   // scatter blocks
static constexpr int VECB   = (NNODE * 16 + 255) / 256;  // init blocks

// ---------------- device scratch (static; no runtime alloc) ----------------
// Invariant: g_wdeg/g_cnt are ZERO at kernel_launch entry (static init covers
// the first call; gatherfinal_kernel re-zeros them at the end of every call).
__device__ float  g_edge_w[NEDGE];
__device__ int    g_rank[NEDGE];            // rank of edge within its dst bucket
__device__ int2   g_edge[NEDGE];            // {src, __float_as_int(edge_w * dinv[src])}
__device__ float  g_wdeg[NNODE];
__device__ float  g_dinv[NNODE];
__device__ int    g_cnt[NNODE];
__device__ int    g_rowptr[NNODE + 1];
__device__ int    g_bsum[SCANB];
__device__ __half g_x0[(size_t)NNODE * DIM];
__device__ __half g_x1[(size_t)NNODE * DIM];
__device__ __half g_x2[(size_t)NNODE * DIM];
__device__ __half* const g_xptr[3] = {g_x0, g_x1, g_x2};

// ---------------- kernels ----------------

// edge gate MLP: sigmoid(relu(f @ W1 + b1) @ w2 + b2).
// Histogram wdeg + cnt; the cnt atomic's RETURN VALUE is the edge's rank
// within its destination bucket -> stored so scatter needs no atomics.
__global__ void mlp_kernel(const float* __restrict__ ef,
                           const float* __restrict__ w1,
                           const float* __restrict__ b1,
                           const float* __restrict__ w2,
                           const float* __restrict__ b2,
                           const int*   __restrict__ eidx) {
    __shared__ float sW1[8 * 32];
    __shared__ float sB1[32];
    __shared__ float sW2[32];
    __shared__ float sB2;
    int t = threadIdx.x;
    if (t < 256) sW1[t] = w1[t];
    if (t < 32)  { sB1[t] = b1[t]; sW2[t] = w2[t]; }
    if (t == 0)  sB2 = b2[0];
    __syncthreads();

    int e = blockIdx.x * blockDim.x + t;
    if (e >= NEDGE) return;

    const float4* fp = reinterpret_cast<const float4*>(ef + (size_t)e * 8);
    float4 fa = __ldg(fp);
    float4 fb = __ldg(fp + 1);
    float f[8] = {fa.x, fa.y, fa.z, fa.w, fb.x, fb.y, fb.z, fb.w};

    float out = sB2;
    #pragma unroll
    for (int j = 0; j < 32; j++) {
        float h = sB1[j];
        #pragma unroll
        for (int i = 0; i < 8; i++) h = fmaf(f[i], sW1[i * 32 + j], h);
        h = fmaxf(h, 0.f);
        out = fmaf(h, sW2[j], out);
    }
    float w = 1.f / (1.f + expf(-out));

    g_edge_w[e] = w;
    int c = __ldg(&eidx[NEDGE + e]);
    atomicAdd(&g_wdeg[c], w);
    g_rank[e] = atomicAdd(&g_cnt[c], 1);
}

// scan phase 1: per-block sums of g_cnt
__global__ void __launch_bounds__(1024) scan1_kernel() {
    __shared__ int sh[1024];
    int n = blockIdx.x * 1024 + threadIdx.x;
    int s = (n < NNODE) ? g_cnt[n] : 0;
    sh[threadIdx.x] = s;
    __syncthreads();
    for (int off = 512; off > 0; off >>= 1) {
        if (threadIdx.x < off) sh[threadIdx.x] += sh[threadIdx.x + off];
        __syncthreads();
    }
    if (threadIdx.x == 0) g_bsum[blockIdx.x] = sh[0];
}

// scan phase 2+3: each block redundantly scans the 147 block sums, then does
// its local exclusive scan and writes rowptr/dinv.
__global__ void __launch_bounds__(1024) scan3_kernel() {
    __shared__ int sums[256];
    __shared__ int sh[1024];
    int t = threadIdx.x;
    if (t < 256) sums[t] = (t < SCANB) ? g_bsum[t] : 0;
    __syncthreads();
    for (int off = 1; off < 256; off <<= 1) {
        int v = (t < 256 && t >= off) ? sums[t - off] : 0;
        __syncthreads();
        if (t < 256) sums[t] += v;
        __syncthreads();
    }
    int blockOff = (blockIdx.x == 0) ? 0 : sums[blockIdx.x - 1];

    int n = blockIdx.x * 1024 + t;
    int c = (n < NNODE) ? g_cnt[n] : 0;
    sh[t] = c;
    __syncthreads();
    for (int off = 1; off < 1024; off <<= 1) {
        int v = (t >= off) ? sh[t - off] : 0;
        __syncthreads();
        sh[t] += v;
        __syncthreads();
    }
    if (n < NNODE) {
        g_rowptr[n] = blockOff + sh[t] - c;
        float dg = g_wdeg[n];
        g_dinv[n] = (dg > 0.f) ? rsqrtf(dg) : 0.f;
    }
    if (blockIdx.x == 0 && t == 0) g_rowptr[NNODE] = NEDGE;
}

// fused scatter + init (ATOMIC-FREE scatter: position = rowptr[dst] + rank):
//   blocks [0, EDGE2B): place edges {src, edge_w*dinv[src]} at their slot
//   blocks [EDGE2B, EDGE2B+VECB): x0 = l2norm(...) node init
__global__ void __launch_bounds__(256) scatterinit_kernel(
        const int*   __restrict__ eidx,
        const float* __restrict__ uemb,  const float* __restrict__ audio,
        const float* __restrict__ art,   const float* __restrict__ alb,
        const int*   __restrict__ aid,   const int*   __restrict__ bid) {
    if (blockIdx.x < EDGE2B) {
        int e = (blockIdx.x * 256 + threadIdx.x) * 2;
        if (e >= NEDGE) return;
        int2   r2 = __ldg(reinterpret_cast<const int2*>(eidx + e));
        int2   c2 = __ldg(reinterpret_cast<const int2*>(eidx + NEDGE + e));
        float2 w2 = __ldg(reinterpret_cast<const float2*>(g_edge_w + e));
        int2   k2 = __ldg(reinterpret_cast<const int2*>(g_rank + e));

        float wa = w2.x * __ldg(&g_dinv[r2.x]);
        g_edge[__ldg(&g_rowptr[c2.x]) + k2.x] = make_int2(r2.x, __float_as_int(wa));

        float wb = w2.y * __ldg(&g_dinv[r2.y]);
        g_edge[__ldg(&g_rowptr[c2.y]) + k2.y] = make_int2(r2.y, __float_as_int(wb));
    } else {
        int t = (blockIdx.x - EDGE2B) * 256 + threadIdx.x;
        int node = t >> 4;
        int sub  = t & 15;
        if (node >= NNODE) return;

        float4 v;
        if (node < NUSERS) {
            v = __ldg(reinterpret_cast<const float4*>(uemb) + (size_t)node * 16 + sub);
        } else {
            int i = node - NUSERS;
            int a = __ldg(&aid[i]);
            int b = __ldg(&bid[i]);
            float4 pa = __ldg(reinterpret_cast<const float4*>(audio) + (size_t)i * 16 + sub);
            float4 pr = __ldg(reinterpret_cast<const float4*>(art)   + (size_t)a * 16 + sub);
            float4 pl = __ldg(reinterpret_cast<const float4*>(alb)   + (size_t)b * 16 + sub);
            v.x = pa.x * 0.3f + (pr.x + pl.x) * 0.44f;
            v.y = pa.y * 0.3f + (pr.y + pl.y) * 0.44f;
            v.z = pa.z * 0.3f + (pr.z + pl.z) * 0.44f;
            v.w = pa.w * 0.3f + (pr.w + pl.w) * 0.44f;
        }
        float ss = v.x * v.x + v.y * v.y + v.z * v.z + v.w * v.w;
        #pragma unroll
        for (int o = 8; o > 0; o >>= 1) ss += __shfl_xor_sync(0xffffffffu, ss, o);
        float inv = 1.f / fmaxf(sqrtf(ss), 1e-12f);

        __half2 h0 = __floats2half2_rn(v.x * inv, v.y * inv);
        __half2 h1 = __floats2half2_rn(v.z * inv, v.w * inv);
        uint2 hv;
        hv.x = *reinterpret_cast<unsigned int*>(&h0);
        hv.y = *reinterpret_cast<unsigned int*>(&h1);
        reinterpret_cast<uint2*>(g_x0)[(size_t)node * 16 + sub] = hv;
    }
}

// ---- gather body: warp = 1 node, lane owns dims {2*lane, 2*lane+1} ----
// Edge meta for up to 32 edges staged in ONE coalesced int2 load; each edge is
// ONE warp-wide 128B row load (4B/lane). 8 independent loads in flight per
// group; padded edges contribute w=0 (src=0 is a valid, safe row).
__device__ __forceinline__ float2 gather_body(const unsigned* __restrict__ xin,
                                              int node, int lane) {
    int rp  = __ldg(&g_rowptr[node + (lane & 1)]);
    int beg = __shfl_sync(0xffffffffu, rp, 0);
    int end = __shfl_sync(0xffffffffu, rp, 1);
    int deg = end - beg;

    float a0 = 0.f, a1 = 0.f;
    for (int base = 0; base < deg; base += 32) {
        int idx = base + lane;
        int2 m = (idx < deg) ? __ldg(&g_edge[beg + idx]) : make_int2(0, 0);
        int nr = (min(deg - base, 32) + 7) & ~7;   // round up to group of 8
        for (int g = 0; g < nr; g += 8) {
            unsigned v[8];
            float    w[8];
            #pragma unroll
            for (int k = 0; k < 8; k++) {
                int src = __shfl_sync(0xffffffffu, m.x, g + k);
                w[k] = __int_as_float(__shfl_sync(0xffffffffu, m.y, g + k));
                v[k] = __ldg(xin + (size_t)src * 32 + lane);
            }
            #pragma unroll
            for (int k = 0; k < 8; k++) {
                float2 f = __half22float2(*reinterpret_cast<__half2*>(&v[k]));
                a0 = fmaf(w[k], f.x, a0);
                a1 = fmaf(w[k], f.y, a1);
            }
        }
    }
    return make_float2(a0, a1);
}

// layers 0,1: x[l+1][n] = dinv[n] * sum  (fp16 out, fully coalesced store)
__global__ void __launch_bounds__(256) gather_kernel(int layer) {
    const unsigned* __restrict__ xin  = reinterpret_cast<const unsigned*>(g_xptr[layer]);
    unsigned*       __restrict__ xout = reinterpret_cast<unsigned*>(g_xptr[layer + 1]);

    int warp = (blockIdx.x * blockDim.x + threadIdx.x) >> 5;
    int lane = threadIdx.x & 31;
    if (warp >= NNODE) return;

    float2 a = gather_body(xin, warp, lane);
    float dv = __ldg(&g_dinv[warp]);
    __half2 h = __floats2half2_rn(a.x * dv, a.y * dv);
    xout[(size_t)warp * 32 + lane] = *reinterpret_cast<unsigned*>(&h);
}

// layer 2 fused with final: out = l2norm((x0+x1+x2+x3)/4), x3 kept fp32.
// Re-establishes zero-invariants (wdeg, cnt) for the next call.
__global__ void __launch_bounds__(256) gatherfinal_kernel(float* __restrict__ out) {
    int gt = blockIdx.x * blockDim.x + threadIdx.x;
    if (gt < NNODE) { g_wdeg[gt] = 0.f; g_cnt[gt] = 0; }
    if (gt == 0) out[(size_t)NNODE * DIM] = 0.f;   // align_loss scalar

    int warp = gt >> 5;
    int lane = threadIdx.x & 31;
    if (warp >= NNODE) return;

    float2 a = gather_body(reinterpret_cast<const unsigned*>(g_x2), warp, lane);
    float dv = __ldg(&g_dinv[warp]);
    float s0 = a.x * dv;
    float s1 = a.y * dv;

    #pragma unroll
    for (int l = 0; l < 3; l++) {
        unsigned v = __ldg(reinterpret_cast<const unsigned*>(g_xptr[l]) + (size_t)warp * 32 + lane);
        float2 f = __half22float2(*reinterpret_cast<__half2*>(&v));
        s0 += f.x;
        s1 += f.y;
    }
    s0 *= 0.25f;
    s1 *= 0.25f;
    float ss = fmaf(s0, s0, s1 * s1);
    #pragma unroll
    for (int o = 16; o > 0; o >>= 1) ss += __shfl_xor_sync(0xffffffffu, ss, o);
    float inv = 1.f / fmaxf(sqrtf(ss), 1e-12f);

    reinterpret_cast<float2*>(out)[(size_t)warp * 32 + lane] = make_float2(s0 * inv, s1 * inv);
}

// ---------------- launcher ----------------
extern "C" void kernel_launch(void* const* d_in, const int* in_sizes, int n_in,
                              void* d_out, int out_size) {
    const float* uemb  = (const float*)d_in[0];
    const float* audio = (const float*)d_in[1];
    const float* art   = (const float*)d_in[2];
    const float* alb   = (const float*)d_in[3];
    const float* w1    = (const float*)d_in[4];
    const float* b1    = (const float*)d_in[5];
    const float* w2    = (const float*)d_in[6];
    const float* b2    = (const float*)d_in[7];
    const float* ef    = (const float*)d_in[8];
    const int*   eidx  = (const int*)  d_in[9];
    const int*   aid   = (const int*)  d_in[10];
    const int*   bid   = (const int*)  d_in[11];
    float* out = (float*)d_out;

    const int edgeBlocks = (NEDGE + 255) / 256;
    const int warpBlocks = (NNODE * 32 + 255) / 256;   // one warp per node

    mlp_kernel        <<<edgeBlocks, 256>>>(ef, w1, b1, w2, b2, eidx);
    scan1_kernel      <<<SCANB, 1024>>>();
    scan3_kernel      <<<SCANB, 1024>>>();
    scatterinit_kernel<<<EDGE2B + VECB, 256>>>(eidx, uemb, audio, art, alb, aid, bid);
    gather_kernel     <<<warpBlocks, 256>>>(0);   // x0 -> x1
    gather_kernel     <<<warpBlocks, 256>>>(1);   // x1 -> x2
    gatherfinal_kernel<<<warpBlocks, 256>>>(out); // x2 -> out (fused final)
}

// round 13
// speedup vs baseline: 1.1894x; 1.0607x over previous
#include <cuda_runtime.h>
#include <cuda_fp16.h>
#include <math.h>
#include <stdint.h>

// ---------------- problem constants ----------------
static constexpr int NUSERS = 100000;
static constexpr int NITEMS = 50000;
static constexpr int NNODE  = 150000;       // NUSERS + NITEMS
static constexpr int NEDGE  = 1200000;      // 2 * 600000
static constexpr int DIM    = 64;
static constexpr int SCANB  = (NNODE + 1023) / 1024;     // 147 scan blocks
static constexpr int EDGE2B = (NEDGE / 2 + 255) / 256;   // scatter blocks
static constexpr int VECB   = (NNODE * 16 + 255) / 256;  // init blocks
static constexpr int GB     = NNODE / 16;                // gather blocks (2 nodes/warp, 8 warps) = 9375

// ---------------- device scratch (static; no runtime alloc) ----------------
// Invariant: g_wdeg/g_cnt are ZERO at kernel_launch entry (static init covers
// the first call; gather layer 0 re-zeros them after scan3 has consumed them).
__device__ float  g_edge_w[NEDGE];
__device__ int    g_rank[NEDGE];            // rank of edge within its dst bucket
__device__ int2   g_edge[NEDGE];            // {src, __float_as_int(edge_w * dinv[src])}
__device__ float  g_wdeg[NNODE];
__device__ float  g_dinv[NNODE];
__device__ int    g_cnt[NNODE];
__device__ int    g_rowptr[NNODE + 1];
__device__ int    g_bsum[SCANB];
__device__ __half g_x0[(size_t)NNODE * DIM];
__device__ __half g_x1[(size_t)NNODE * DIM];
__device__ __half g_x2[(size_t)NNODE * DIM];
__device__ __half* const g_xptr[3] = {g_x0, g_x1, g_x2};

// ---------------- kernels ----------------

// edge gate MLP: sigmoid(relu(f @ W1 + b1) @ w2 + b2).
// Histogram wdeg + cnt; the cnt atomic's RETURN VALUE is the edge's rank
// within its destination bucket -> stored so scatter needs no atomics.
__global__ void mlp_kernel(const float* __restrict__ ef,
                           const float* __restrict__ w1,
                           const float* __restrict__ b1,
                           const float* __restrict__ w2,
                           const float* __restrict__ b2,
                           const int*   __restrict__ eidx) {
    __shared__ float sW1[8 * 32];
    __shared__ float sB1[32];
    __shared__ float sW2[32];
    __shared__ float sB2;
    int t = threadIdx.x;
    if (t < 256) sW1[t] = w1[t];
    if (t < 32)  { sB1[t] = b1[t]; sW2[t] = w2[t]; }
    if (t == 0)  sB2 = b2[0];
    __syncthreads();

    int e = blockIdx.x * blockDim.x + t;
    if (e >= NEDGE) return;

    const float4* fp = reinterpret_cast<const float4*>(ef + (size_t)e * 8);
    float4 fa = __ldg(fp);
    float4 fb = __ldg(fp + 1);
    float f[8] = {fa.x, fa.y, fa.z, fa.w, fb.x, fb.y, fb.z, fb.w};

    float out = sB2;
    #pragma unroll
    for (int j = 0; j < 32; j++) {
        float h = sB1[j];
        #pragma unroll
        for (int i = 0; i < 8; i++) h = fmaf(f[i], sW1[i * 32 + j], h);
        h = fmaxf(h, 0.f);
        out = fmaf(h, sW2[j], out);
    }
    float w = 1.f / (1.f + expf(-out));

    g_edge_w[e] = w;
    int c = __ldg(&eidx[NEDGE + e]);
    atomicAdd(&g_wdeg[c], w);
    g_rank[e] = atomicAdd(&g_cnt[c], 1);
}

// scan phase 1: per-block sums of g_cnt
__global__ void __launch_bounds__(1024) scan1_kernel() {
    __shared__ int sh[1024];
    int n = blockIdx.x * 1024 + threadIdx.x;
    int s = (n < NNODE) ? g_cnt[n] : 0;
    sh[threadIdx.x] = s;
    __syncthreads();
    for (int off = 512; off > 0; off >>= 1) {
        if (threadIdx.x < off) sh[threadIdx.x] += sh[threadIdx.x + off];
        __syncthreads();
    }
    if (threadIdx.x == 0) g_bsum[blockIdx.x] = sh[0];
}

// scan phase 2+3: each block redundantly scans the 147 block sums, then does
// its local exclusive scan and writes rowptr/dinv.
__global__ void __launch_bounds__(1024) scan3_kernel() {
    __shared__ int sums[256];
    __shared__ int sh[1024];
    int t = threadIdx.x;
    if (t < 256) sums[t] = (t < SCANB) ? g_bsum[t] : 0;
    __syncthreads();
    for (int off = 1; off < 256; off <<= 1) {
        int v = (t < 256 && t >= off) ? sums[t - off] : 0;
        __syncthreads();
        if (t < 256) sums[t] += v;
        __syncthreads();
    }
    int blockOff = (blockIdx.x == 0) ? 0 : sums[blockIdx.x - 1];

    int n = blockIdx.x * 1024 + t;
    int c = (n < NNODE) ? g_cnt[n] : 0;
    sh[t] = c;
    __syncthreads();
    for (int off = 1; off < 1024; off <<= 1) {
        int v = (t >= off) ? sh[t - off] : 0;
        __syncthreads();
        sh[t] += v;
        __syncthreads();
    }
    if (n < NNODE) {
        g_rowptr[n] = blockOff + sh[t] - c;
        float dg = g_wdeg[n];
        g_dinv[n] = (dg > 0.f) ? rsqrtf(dg) : 0.f;
    }
    if (blockIdx.x == 0 && t == 0) g_rowptr[NNODE] = NEDGE;
}

// fused scatter + init (ATOMIC-FREE scatter: position = rowptr[dst] + rank):
//   blocks [0, EDGE2B): place edges {src, edge_w*dinv[src]} at their slot
//   blocks [EDGE2B, EDGE2B+VECB): x0 = l2norm(...) node init
__global__ void __launch_bounds__(256) scatterinit_kernel(
        const int*   __restrict__ eidx,
        const float* __restrict__ uemb,  const float* __restrict__ audio,
        const float* __restrict__ art,   const float* __restrict__ alb,
        const int*   __restrict__ aid,   const int*   __restrict__ bid) {
    if (blockIdx.x < EDGE2B) {
        int e = (blockIdx.x * 256 + threadIdx.x) * 2;
        if (e >= NEDGE) return;
        int2   r2 = __ldg(reinterpret_cast<const int2*>(eidx + e));
        int2   c2 = __ldg(reinterpret_cast<const int2*>(eidx + NEDGE + e));
        float2 w2 = __ldg(reinterpret_cast<const float2*>(g_edge_w + e));
        int2   k2 = __ldg(reinterpret_cast<const int2*>(g_rank + e));

        float wa = w2.x * __ldg(&g_dinv[r2.x]);
        g_edge[__ldg(&g_rowptr[c2.x]) + k2.x] = make_int2(r2.x, __float_as_int(wa));

        float wb = w2.y * __ldg(&g_dinv[r2.y]);
        g_edge[__ldg(&g_rowptr[c2.y]) + k2.y] = make_int2(r2.y, __float_as_int(wb));
    } else {
        int t = (blockIdx.x - EDGE2B) * 256 + threadIdx.x;
        int node = t >> 4;
        int sub  = t & 15;
        if (node >= NNODE) return;

        float4 v;
        if (node < NUSERS) {
            v = __ldg(reinterpret_cast<const float4*>(uemb) + (size_t)node * 16 + sub);
        } else {
            int i = node - NUSERS;
            int a = __ldg(&aid[i]);
            int b = __ldg(&bid[i]);
            float4 pa = __ldg(reinterpret_cast<const float4*>(audio) + (size_t)i * 16 + sub);
            float4 pr = __ldg(reinterpret_cast<const float4*>(art)   + (size_t)a * 16 + sub);
            float4 pl = __ldg(reinterpret_cast<const float4*>(alb)   + (size_t)b * 16 + sub);
            v.x = pa.x * 0.3f + (pr.x + pl.x) * 0.44f;
            v.y = pa.y * 0.3f + (pr.y + pl.y) * 0.44f;
            v.z = pa.z * 0.3f + (pr.z + pl.z) * 0.44f;
            v.w = pa.w * 0.3f + (pr.w + pl.w) * 0.44f;
        }
        float ss = v.x * v.x + v.y * v.y + v.z * v.z + v.w * v.w;
        #pragma unroll
        for (int o = 8; o > 0; o >>= 1) ss += __shfl_xor_sync(0xffffffffu, ss, o);
        float inv = 1.f / fmaxf(sqrtf(ss), 1e-12f);

        __half2 h0 = __floats2half2_rn(v.x * inv, v.y * inv);
        __half2 h1 = __floats2half2_rn(v.z * inv, v.w * inv);
        uint2 hv;
        hv.x = *reinterpret_cast<unsigned int*>(&h0);
        hv.y = *reinterpret_cast<unsigned int*>(&h1);
        reinterpret_cast<uint2*>(g_x0)[(size_t)node * 16 + sub] = hv;
    }
}

// ---- gather segment: lane owns dims {2*lane, 2*lane+1} of the dst node ----
// Edge meta for up to 32 edges staged in ONE coalesced int2 load; each edge is
// ONE warp-wide 128B row load (4B/lane). 8 independent loads in flight per
// group; padded edges contribute w=0 (src=0 is a valid, safe row).
__device__ __forceinline__ float2 gather_seg(const unsigned* __restrict__ xin,
                                             int beg, int end, int lane) {
    float a0 = 0.f, a1 = 0.f;
    for (int base = beg; base < end; base += 32) {
        int idx = base + lane;
        int2 m = (idx < end) ? __ldg(&g_edge[idx]) : make_int2(0, 0);
        int nr = (min(end - base, 32) + 7) & ~7;   // round up to group of 8
        for (int g = 0; g < nr; g += 8) {
            unsigned v[8];
            float    w[8];
            #pragma unroll
            for (int k = 0; k < 8; k++) {
                int src = __shfl_sync(0xffffffffu, m.x, g + k);
                w[k] = __int_as_float(__shfl_sync(0xffffffffu, m.y, g + k));
                v[k] = __ldg(xin + (size_t)src * 32 + lane);
            }
            #pragma unroll
            for (int k = 0; k < 8; k++) {
                float2 f = __half22float2(*reinterpret_cast<__half2*>(&v[k]));
                a0 = fmaf(w[k], f.x, a0);
                a1 = fmaf(w[k], f.y, a1);
            }
        }
    }
    return make_float2(a0, a1);
}

// layers 0,1: x[l+1][n] = dinv[n] * sum.  Warp = 2 consecutive nodes (adjacent
// CSR segments); shared prologue. Layer 0 also re-zeros wdeg/cnt (post-scan).
__global__ void __launch_bounds__(256) gather_kernel(int layer) {
    const unsigned* __restrict__ xin  = reinterpret_cast<const unsigned*>(g_xptr[layer]);
    unsigned*       __restrict__ xout = reinterpret_cast<unsigned*>(g_xptr[layer + 1]);

    int gt = blockIdx.x * blockDim.x + threadIdx.x;
    if (layer == 0 && gt < NNODE) { g_wdeg[gt] = 0.f; g_cnt[gt] = 0; }

    int lane = threadIdx.x & 31;
    int n0 = (gt >> 5) * 2;                       // 2 nodes per warp

    int rp = __ldg(&g_rowptr[n0 + min(lane, 2)]);
    int beg = __shfl_sync(0xffffffffu, rp, 0);
    int mid = __shfl_sync(0xffffffffu, rp, 1);
    int end = __shfl_sync(0xffffffffu, rp, 2);
    float dvl = __ldg(&g_dinv[n0 + (lane & 1)]);
    float dv0 = __shfl_sync(0xffffffffu, dvl, 0);
    float dv1 = __shfl_sync(0xffffffffu, dvl, 1);

    float2 a = gather_seg(xin, beg, mid, lane);
    __half2 h0 = __floats2half2_rn(a.x * dv0, a.y * dv0);
    xout[(size_t)n0 * 32 + lane] = *reinterpret_cast<unsigned*>(&h0);

    float2 b = gather_seg(xin, mid, end, lane);
    __half2 h1 = __floats2half2_rn(b.x * dv1, b.y * dv1);
    xout[(size_t)(n0 + 1) * 32 + lane] = *reinterpret_cast<unsigned*>(&h1);
}

// layer 2 fused with final: out = l2norm((x0+x1+x2+x3)/4), x3 kept fp32.
__global__ void __launch_bounds__(256) gatherfinal_kernel(float* __restrict__ out) {
    int gt = blockIdx.x * blockDim.x + threadIdx.x;
    if (gt == 0) out[(size_t)NNODE * DIM] = 0.f;   // align_loss scalar

    int lane = threadIdx.x & 31;
    int n0 = (gt >> 5) * 2;

    int rp = __ldg(&g_rowptr[n0 + min(lane, 2)]);
    int beg = __shfl_sync(0xffffffffu, rp, 0);
    int mid = __shfl_sync(0xffffffffu, rp, 1);
    int end = __shfl_sync(0xffffffffu, rp, 2);
    float dvl = __ldg(&g_dinv[n0 + (lane & 1)]);
    float dv0 = __shfl_sync(0xffffffffu, dvl, 0);
    float dv1 = __shfl_sync(0xffffffffu, dvl, 1);

    const unsigned* x2p = reinterpret_cast<const unsigned*>(g_x2);
    float2 a = gather_seg(x2p, beg, mid, lane);
    float2 b = gather_seg(x2p, mid, end, lane);

    float s0 = a.x * dv0, s1 = a.y * dv0;   // node n0
    float t0 = b.x * dv1, t1 = b.y * dv1;   // node n0+1

    #pragma unroll
    for (int l = 0; l < 3; l++) {
        const unsigned* xp = reinterpret_cast<const unsigned*>(g_xptr[l]);
        unsigned va = __ldg(xp + (size_t)n0 * 32 + lane);
        unsigned vb = __ldg(xp + (size_t)(n0 + 1) * 32 + lane);
        float2 fa = __half22float2(*reinterpret_cast<__half2*>(&va));
        float2 fb = __half22float2(*reinterpret_cast<__half2*>(&vb));
        s0 += fa.x; s1 += fa.y;
        t0 += fb.x; t1 += fb.y;
    }
    s0 *= 0.25f; s1 *= 0.25f; t0 *= 0.25f; t1 *= 0.25f;
    float ssA = fmaf(s0, s0, s1 * s1);
    float ssB = fmaf(t0, t0, t1 * t1);
    #pragma unroll
    for (int o = 16; o > 0; o >>= 1) {
        ssA += __shfl_xor_sync(0xffffffffu, ssA, o);
        ssB += __shfl_xor_sync(0xffffffffu, ssB, o);
    }
    float invA = 1.f / fmaxf(sqrtf(ssA), 1e-12f);
    float invB = 1.f / fmaxf(sqrtf(ssB), 1e-12f);

    float2* op = reinterpret_cast<float2*>(out);
    op[(size_t)n0 * 32 + lane]       = make_float2(s0 * invA, s1 * invA);
    op[(size_t)(n0 + 1) * 32 + lane] = make_float2(t0 * invB, t1 * invB);
}

// ---------------- launcher ----------------
extern "C" void kernel_launch(void* const* d_in, const int* in_sizes, int n_in,
                              void* d_out, int out_size) {
    const float* uemb  = (const float*)d_in[0];
    const float* audio = (const float*)d_in[1];
    const float* art   = (const float*)d_in[2];
    const float* alb   = (const float*)d_in[3];
    const float* w1    = (const float*)d_in[4];
    const float* b1    = (const float*)d_in[5];
    const float* w2    = (const float*)d_in[6];
    const float* b2    = (const float*)d_in[7];
    const float* ef    = (const float*)d_in[8];
    const int*   eidx  = (const int*)  d_in[9];
    const int*   aid   = (const int*)  d_in[10];
    const int*   bid   = (const int*)  d_in[11];
    float* out = (float*)d_out;

    const int edgeBlocks = (NEDGE + 255) / 256;

    mlp_kernel        <<<edgeBlocks, 256>>>(ef, w1, b1, w2, b2, eidx);
    scan1_kernel      <<<SCANB, 1024>>>();
    scan3_kernel      <<<SCANB, 1024>>>();
    scatterinit_kernel<<<EDGE2B + VECB, 256>>>(eidx, uemb, audio, art, alb, aid, bid);
    gather_kernel     <<<GB, 256>>>(0);   // x0 -> x1  (also re-zeros wdeg/cnt)
    gather_kernel     <<<GB, 256>>>(1);   // x1 -> x2
    gatherfinal_kernel<<<GB, 256>>>(out); // x2 -> out (fused final)
}